// round 3
// baseline (speedup 1.0000x reference)
#include <cuda_runtime.h>
#include <math.h>
#include <cstdint>

// Problem constants (fixed by the reference: B=32, T=8192, K=16)
#define BT_ROWS   (32 * 8192)     // 262144 rows
#define KDIM      16
#define NBLK      1024
#define NTHR      256             // NBLK*NTHR == BT_ROWS exactly
#define EPS_F     1e-7f

// Per-block partial sums: [6][NBLK]
__device__ double g_part[6 * NBLK];
// live_mask dtype mode: 0 = uint8/bool bytes, 1 = int32 words, 2 = float32 words
__device__ int g_live_mode;

__device__ __forceinline__ double warp_sum_d(double v) {
#pragma unroll
    for (int o = 16; o > 0; o >>= 1)
        v += __shfl_down_sync(0xffffffffu, v, o);
    return v;
}

// ---- Prologue: detect how the harness materialized the bool live_mask ----
__global__ void detect_live_mode(const unsigned int* __restrict__ w)
{
    __shared__ unsigned int s_or;        // OR of all words (excluding f32 ones)
    __shared__ int s_f32;
    if (threadIdx.x == 0) { s_or = 0u; s_f32 = 0; }
    __syncthreads();
    unsigned int acc = 0u; int f32 = 0;
    // scan 16384 words = 64KB; enough to see every byte lane many times
    for (int i = threadIdx.x; i < 16384; i += blockDim.x) {
        unsigned int x = w[i];
        if (x == 0x3F800000u) f32 = 1;
        else acc |= x;
    }
#pragma unroll
    for (int o = 16; o > 0; o >>= 1) {
        acc |= __shfl_down_sync(0xffffffffu, acc, o);
        f32 |= __shfl_down_sync(0xffffffffu, f32, o);
    }
    if ((threadIdx.x & 31) == 0) {
        atomicOr(&s_or, acc);
        if (f32) atomicOr((unsigned int*)&s_f32, 1u);
    }
    __syncthreads();
    if (threadIdx.x == 0) {
        int mode;
        if (s_f32)                 mode = 2;  // float32 0.0/1.0
        else if (s_or & ~1u)       mode = 0;  // packed bytes (any byte>0 above bit0)
        else                       mode = 1;  // int32 words 0/1
        g_live_mode = mode;
    }
}

__global__ __launch_bounds__(NTHR)
void lifecycle_main(const float* __restrict__ trig,          // (B,T,K)
                    const float* __restrict__ vld,           // (B,T,K)
                    const float* __restrict__ clog,          // (B,T,K,3)
                    const float* __restrict__ wsc,           // (B,T,1)
                    const void*  __restrict__ live_raw,      // (B,T,K) bool (dtype per g_live_mode)
                    const int*   __restrict__ cid,           // (B,T,K)
                    const float* __restrict__ ofire,         // (B,T,K)
                    const int*   __restrict__ ocan,          // (B,T,K)
                    const float* __restrict__ ovld,          // (B,T,K)
                    const float* __restrict__ osw,           // (B,T,1)
                    const int*   __restrict__ ocid)          // (B,T,K)
{
    const int row  = blockIdx.x * NTHR + threadIdx.x;
    const int base = row * KDIM;

    // ---- Contract ids (model + oracle), vectorized ----
    int oc[KDIM], cd[KDIM];
#pragma unroll
    for (int g = 0; g < 4; ++g) {
        int4 io = ((const int4*)(ocid + base))[g];
        int4 ic = ((const int4*)(cid  + base))[g];
        oc[4*g+0] = io.x; oc[4*g+1] = io.y; oc[4*g+2] = io.z; oc[4*g+3] = io.w;
        cd[4*g+0] = ic.x; cd[4*g+1] = ic.y; cd[4*g+2] = ic.z; cd[4*g+3] = ic.w;
    }

    // ---- live mask -> 16-bit mask, honoring detected dtype ----
    const int mode = g_live_mode;   // uniform across grid
    unsigned int lmask = 0u;
    if (mode == 0) {
        uint4 L = *((const uint4*)((const unsigned char*)live_raw + base));
        unsigned int w[4] = {L.x, L.y, L.z, L.w};
#pragma unroll
        for (int k = 0; k < KDIM; ++k)
            if ((w[k >> 2] >> (8 * (k & 3))) & 0xFFu) lmask |= (1u << k);
    } else if (mode == 1) {
        const int* lp = (const int*)live_raw + base;
#pragma unroll
        for (int g = 0; g < 4; ++g) {
            int4 w = ((const int4*)lp)[g];
            if (w.x) lmask |= 1u << (4*g+0);
            if (w.y) lmask |= 1u << (4*g+1);
            if (w.z) lmask |= 1u << (4*g+2);
            if (w.w) lmask |= 1u << (4*g+3);
        }
    } else {
        const float* lp = (const float*)live_raw + base;
#pragma unroll
        for (int g = 0; g < 4; ++g) {
            float4 w = ((const float4*)lp)[g];
            if (w.x != 0.0f) lmask |= 1u << (4*g+0);
            if (w.y != 0.0f) lmask |= 1u << (4*g+1);
            if (w.z != 0.0f) lmask |= 1u << (4*g+2);
            if (w.w != 0.0f) lmask |= 1u << (4*g+3);
        }
    }

    double fire_s = 0.0, m_s = 0.0, val_s = 0.0, can_s = 0.0, has_s = 0.0;

#pragma unroll
    for (int km = 0; km < KDIM; ++km) {
        // First-match scan (reference: argmax over boolean -> FIRST matching ko)
        const int c = cd[km];
        int idx = -1;
#pragma unroll
        for (int ko = KDIM - 1; ko >= 0; --ko)
            if (oc[ko] == c) idx = ko;
        const bool fnd = (idx >= 0) && (c != 0);
        const int  gix = base + (fnd ? idx : 0);

        if ((lmask >> km) & 1u) {
            m_s += 1.0;

            const float tf = fnd ? ofire[gix] : 0.0f;
            const float tv = fnd ? ovld[gix] : 0.0f;
            const int   ct = fnd ? ocan[gix] : 0;

            // fire BCE: exact reference form
            float p   = fminf(fmaxf(trig[base + km], EPS_F), 1.0f - EPS_F);
            float lp  = logf(p);
            float l1p = logf(fmaxf(1.0f - p, EPS_F));
            fire_s += (double)(-(tf * lp + (1.0f - tf) * l1p));

            // valid BCE
            float q   = fminf(fmaxf(vld[base + km], EPS_F), 1.0f - EPS_F);
            float lq  = logf(q);
            float l1q = logf(fmaxf(1.0f - q, EPS_F));
            val_s += (double)(-(tv * lq + (1.0f - tv) * l1q));

            // cancel CE (only where aligned cancel target > 0)
            if (ct > 0) {
                const float* lpp = clog + (size_t)(base + km) * 3;
                float x0 = lpp[0], x1 = lpp[1], x2 = lpp[2];
                float mx = fmaxf(x0, fmaxf(x1, x2));
                float s  = expf(x0 - mx) + expf(x1 - mx) + expf(x2 - mx);
                int tgt  = ct - 1;
                tgt = tgt < 0 ? 0 : (tgt > 2 ? 2 : tgt);
                float xt = (tgt == 0) ? x0 : ((tgt == 1) ? x1 : x2);
                can_s += (double)(mx + logf(s) - xt);
                has_s += 1.0;
            }
        }
    }

    // write-head BCE-with-logits (one element per row)
    float wx = wsc[row], wy = osw[row];
    double w_s = (double)(fmaxf(wx, 0.0f) - wx * wy + log1pf(expf(-fabsf(wx))));

    // ---- Deterministic block reduction of 6 double accumulators ----
    __shared__ double sm[8][6];
    double vals[6] = {fire_s, m_s, val_s, can_s, has_s, w_s};
#pragma unroll
    for (int j = 0; j < 6; ++j) vals[j] = warp_sum_d(vals[j]);
    const int wid = threadIdx.x >> 5, lid = threadIdx.x & 31;
    if (lid == 0) {
#pragma unroll
        for (int j = 0; j < 6; ++j) sm[wid][j] = vals[j];
    }
    __syncthreads();
    if (wid == 0) {
#pragma unroll
        for (int j = 0; j < 6; ++j) {
            double v = (lid < (NTHR / 32)) ? sm[lid][j] : 0.0;
            v = warp_sum_d(v);
            if (lid == 0) g_part[j * NBLK + blockIdx.x] = v;
        }
    }
}

__global__ __launch_bounds__(256)
void lifecycle_finalize(float* __restrict__ out)
{
    __shared__ double sm[8];
    double tot[6];
#pragma unroll
    for (int j = 0; j < 6; ++j) {
        double v = 0.0;
        for (int i = threadIdx.x; i < NBLK; i += 256)
            v += g_part[j * NBLK + i];
        v = warp_sum_d(v);
        const int wid = threadIdx.x >> 5, lid = threadIdx.x & 31;
        if (lid == 0) sm[wid] = v;
        __syncthreads();
        double r = 0.0;
        if (wid == 0) {
            r = (lid < 8) ? sm[lid] : 0.0;
            r = warp_sum_d(r);
        }
        tot[j] = r;  // valid on thread 0
        __syncthreads();
    }
    if (threadIdx.x == 0) {
        double n     = fmax(tot[1], 1.0);
        double fire  = tot[0] / n;                                        // LAM_FIRE   = 1.0
        double canc  = (tot[4] > 0.0) ? tot[3] / fmax(tot[4], 1.0) : 0.0; // LAM_CANCEL = 1.0
        double valid = 0.5 * tot[2] / n;                                  // LAM_VALID  = 0.5
        double wr    = 0.5 * tot[5] / (double)BT_ROWS;                    // LAM_WRITE  = 0.5
        out[0] = (float)fire;
        out[1] = (float)canc;
        out[2] = (float)valid;
        out[3] = (float)wr;
        out[4] = (float)(fire + canc + valid + wr);
    }
}

extern "C" void kernel_launch(void* const* d_in, const int* in_sizes, int n_in,
                              void* d_out, int out_size)
{
    (void)in_sizes; (void)n_in; (void)out_size;
    detect_live_mode<<<1, 256>>>((const unsigned int*)d_in[4]);
    lifecycle_main<<<NBLK, NTHR>>>(
        (const float*)d_in[0],          // trigger_hazard
        (const float*)d_in[1],          // validity
        (const float*)d_in[2],          // cancel_logits
        (const float*)d_in[3],          // write_score
        d_in[4],                        // live_mask (dtype auto-detected)
        (const int*)d_in[5],            // contract_id
        (const float*)d_in[6],          // oracle_fire
        (const int*)d_in[7],            // oracle_cancel
        (const float*)d_in[8],          // oracle_valid
        (const float*)d_in[9],          // oracle_should_write
        (const int*)d_in[10]);          // oracle_contract_id
    lifecycle_finalize<<<1, 256>>>((float*)d_out);
}

// round 4
// speedup vs baseline: 1.6560x; 1.6560x over previous
#include <cuda_runtime.h>
#include <math.h>
#include <cstdint>

// Problem constants (fixed by reference: B=32, T=8192, K=16)
#define BT_ROWS   (32 * 8192)            // 262144 rows
#define KDIM      16
#define ELEMS     (BT_ROWS * KDIM)       // 4194304
#define NBLK      2048
#define NTHR      256
#define STRIDE    (NBLK * NTHR)          // 524288
#define ITER      (ELEMS / STRIDE)       // 8, exact
#define EPS_F     1e-7f

// Per-block partial sums: [6][NBLK]
// j=0 fire_bce, j=1 live_count, j=2 valid_bce, j=3 cancel_ce, j=4 has_count, j=5 write_bce
__device__ float g_part[6 * NBLK];

__device__ __forceinline__ float warp_sum_f(float v) {
#pragma unroll
    for (int o = 16; o > 0; o >>= 1)
        v += __shfl_down_sync(0xffffffffu, v, o);
    return v;
}
__device__ __forceinline__ double warp_sum_d(double v) {
#pragma unroll
    for (int o = 16; o > 0; o >>= 1)
        v += __shfl_down_sync(0xffffffffu, v, o);
    return v;
}

__global__ __launch_bounds__(NTHR)
void lifecycle_main(const float* __restrict__ trig,          // (B,T,K)
                    const float* __restrict__ vld,           // (B,T,K)
                    const float* __restrict__ clog,          // (B,T,K,3)
                    const float* __restrict__ wsc,           // (B,T,1)
                    const void*  __restrict__ live_raw,      // (B,T,K) bool, dtype unknown
                    const int*   __restrict__ cid,           // (B,T,K)
                    const float* __restrict__ ofire,         // (B,T,K)
                    const int*   __restrict__ ocan,          // (B,T,K)
                    const float* __restrict__ ovld,          // (B,T,K)
                    const float* __restrict__ osw,           // (B,T,1)
                    const int*   __restrict__ ocid)          // (B,T,K)
{
    // ---- Inline live_mask dtype detection (all blocks read same 64 words; L2 hit) ----
    // mode 0 = uint8 bytes, 1 = int32 words, 2 = float32 words
    __shared__ unsigned int s_or, s_f32;
    __shared__ int s_mode;
    if (threadIdx.x == 0) { s_or = 0u; s_f32 = 0u; }
    __syncthreads();
    if (threadIdx.x < 64) {
        unsigned int x = ((const unsigned int*)live_raw)[threadIdx.x];
        unsigned int f = (x == 0x3F800000u) ? 1u : 0u;
        unsigned int a = f ? 0u : x;
#pragma unroll
        for (int o = 16; o > 0; o >>= 1) {
            a |= __shfl_down_sync(0xffffffffu, a, o);
            f |= __shfl_down_sync(0xffffffffu, f, o);
        }
        if ((threadIdx.x & 31) == 0) { atomicOr(&s_or, a); atomicOr(&s_f32, f); }
    }
    __syncthreads();
    if (threadIdx.x == 0)
        s_mode = s_f32 ? 2 : ((s_or & ~1u) ? 0 : 1);
    __syncthreads();
    const int mode = s_mode;

    const unsigned int lane  = threadIdx.x & 31;
    const unsigned int gbase = lane & ~15u;   // 16-lane row group base within warp

    float fire_s = 0.f, m_s = 0.f, val_s = 0.f, can_s = 0.f, has_s = 0.f, w_s = 0.f;

    int e = blockIdx.x * NTHR + threadIdx.x;  // element index; lane k = e & 15 (stable)
#pragma unroll
    for (int it = 0; it < ITER; ++it, e += STRIDE) {
        const int row = e >> 4;
        const int k   = e & 15;

        // Coalesced per-element loads
        const int   c  = cid[e];
        const int   o  = ocid[e];
        const float th = trig[e];
        const float vv = vld[e];
        const float tf_own = ofire[e];
        const float tv_own = ovld[e];
        const int   ct_own = ocan[e];

        // live flag per detected dtype (uniform branch)
        bool lm;
        if (mode == 0)      lm = ((const unsigned char*)live_raw)[e] != 0;
        else if (mode == 1) lm = ((const int*)live_raw)[e] != 0;
        else                lm = ((const float*)live_raw)[e] != 0.0f;

        // First-match scan across the 16-lane group via shuffles
        int idx16 = 16;
#pragma unroll
        for (int ko = 15; ko >= 0; --ko) {
            int ov = __shfl_sync(0xffffffffu, o, gbase + ko, 32);
            if (ov == c) idx16 = ko;
        }
        const bool fnd = (idx16 < 16) && (c != 0);
        const int  src = gbase + (fnd ? idx16 : 0);

        // Gather oracle targets via shuffle (lanes already hold them)
        float tf = __shfl_sync(0xffffffffu, tf_own, src, 32);
        float tv = __shfl_sync(0xffffffffu, tv_own, src, 32);
        int   ct = __shfl_sync(0xffffffffu, ct_own, src, 32);
        if (!fnd) { tf = 0.f; tv = 0.f; ct = 0; }

        if (lm) {
            m_s += 1.0f;

            float p = fminf(fmaxf(th, EPS_F), 1.0f - EPS_F);
            fire_s -= tf * __logf(p) + (1.0f - tf) * __logf(1.0f - p);

            float q = fminf(fmaxf(vv, EPS_F), 1.0f - EPS_F);
            val_s -= tv * __logf(q) + (1.0f - tv) * __logf(1.0f - q);

            if (ct > 0) {
                const float* lp = clog + (size_t)e * 3;
                float x0 = lp[0], x1 = lp[1], x2 = lp[2];
                float mx = fmaxf(x0, fmaxf(x1, x2));
                float s  = __expf(x0 - mx) + __expf(x1 - mx) + __expf(x2 - mx);
                int tgt = ct - 1;                 // ocan in 0..3 -> tgt 0..2
                tgt = tgt < 0 ? 0 : (tgt > 2 ? 2 : tgt);
                float xt = (tgt == 0) ? x0 : ((tgt == 1) ? x1 : x2);
                can_s += mx + __logf(s) - xt;
                has_s += 1.0f;
            }
        }

        // write-head BCE-with-logits: one per row (lane with k==0)
        if (k == 0) {
            float wx = wsc[row], wy = osw[row];
            w_s += fmaxf(wx, 0.0f) - wx * wy + __logf(1.0f + __expf(-fabsf(wx)));
        }
    }

    // ---- Deterministic block reduction of 6 float accumulators ----
    __shared__ float sm[8][6];
    float vals[6] = {fire_s, m_s, val_s, can_s, has_s, w_s};
#pragma unroll
    for (int j = 0; j < 6; ++j) vals[j] = warp_sum_f(vals[j]);
    const int wid = threadIdx.x >> 5, lid = threadIdx.x & 31;
    if (lid == 0) {
#pragma unroll
        for (int j = 0; j < 6; ++j) sm[wid][j] = vals[j];
    }
    __syncthreads();
    if (wid == 0) {
#pragma unroll
        for (int j = 0; j < 6; ++j) {
            float v = (lid < (NTHR / 32)) ? sm[lid][j] : 0.0f;
            v = warp_sum_f(v);
            if (lid == 0) g_part[j * NBLK + blockIdx.x] = v;
        }
    }
}

__global__ __launch_bounds__(256)
void lifecycle_finalize(float* __restrict__ out)
{
    __shared__ double sm[8];
    double tot[6];
#pragma unroll
    for (int j = 0; j < 6; ++j) {
        double v = 0.0;
        for (int i = threadIdx.x; i < NBLK; i += 256)
            v += (double)g_part[j * NBLK + i];
        v = warp_sum_d(v);
        const int wid = threadIdx.x >> 5, lid = threadIdx.x & 31;
        if (lid == 0) sm[wid] = v;
        __syncthreads();
        double r = 0.0;
        if (wid == 0) {
            r = (lid < 8) ? sm[lid] : 0.0;
            r = warp_sum_d(r);
        }
        tot[j] = r;  // valid on thread 0
        __syncthreads();
    }
    if (threadIdx.x == 0) {
        double n     = fmax(tot[1], 1.0);
        double fire  = tot[0] / n;                                        // LAM_FIRE   = 1.0
        double canc  = (tot[4] > 0.0) ? tot[3] / fmax(tot[4], 1.0) : 0.0; // LAM_CANCEL = 1.0
        double valid = 0.5 * tot[2] / n;                                  // LAM_VALID  = 0.5
        double wr    = 0.5 * tot[5] / (double)BT_ROWS;                    // LAM_WRITE  = 0.5
        out[0] = (float)fire;
        out[1] = (float)canc;
        out[2] = (float)valid;
        out[3] = (float)wr;
        out[4] = (float)(fire + canc + valid + wr);
    }
}

extern "C" void kernel_launch(void* const* d_in, const int* in_sizes, int n_in,
                              void* d_out, int out_size)
{
    (void)in_sizes; (void)n_in; (void)out_size;
    lifecycle_main<<<NBLK, NTHR>>>(
        (const float*)d_in[0],          // trigger_hazard
        (const float*)d_in[1],          // validity
        (const float*)d_in[2],          // cancel_logits
        (const float*)d_in[3],          // write_score
        d_in[4],                        // live_mask (dtype auto-detected)
        (const int*)d_in[5],            // contract_id
        (const float*)d_in[6],          // oracle_fire
        (const int*)d_in[7],            // oracle_cancel
        (const float*)d_in[8],          // oracle_valid
        (const float*)d_in[9],          // oracle_should_write
        (const int*)d_in[10]);          // oracle_contract_id
    lifecycle_finalize<<<1, 256>>>((float*)d_out);
}

// round 5
// speedup vs baseline: 1.6664x; 1.0062x over previous
#include <cuda_runtime.h>
#include <math.h>
#include <cstdint>

// Problem constants (fixed by reference: B=32, T=8192, K=16)
#define BT_ROWS   (32 * 8192)            // 262144 rows
#define KDIM      16
#define ELEMS     (BT_ROWS * KDIM)       // 4194304
#define NBLK      2048
#define NTHR      256
#define NTHREADS  (NBLK * NTHR)          // 524288 threads
#define GROUPS    (ELEMS / 4)            // 1048576 four-elem groups
#define ITER      (GROUPS / NTHREADS)    // 2, exact
#define EPS_F     1e-7f
#define FULLMASK  0xffffffffu

// Per-block partial sums: [6][NBLK]
// j=0 fire_bce, j=1 live_count, j=2 valid_bce, j=3 cancel_ce, j=4 has_count, j=5 write_bce
__device__ float g_part[6 * NBLK];
__device__ unsigned int g_sem;   // zero-initialized; reset by last block each launch

__device__ __forceinline__ float warp_sum_f(float v) {
#pragma unroll
    for (int o = 16; o > 0; o >>= 1)
        v += __shfl_down_sync(FULLMASK, v, o);
    return v;
}
__device__ __forceinline__ double warp_sum_d(double v) {
#pragma unroll
    for (int o = 16; o > 0; o >>= 1)
        v += __shfl_down_sync(FULLMASK, v, o);
    return v;
}

__global__ __launch_bounds__(NTHR)
void lifecycle_fused(const float* __restrict__ trig,          // (B,T,K)
                     const float* __restrict__ vld,           // (B,T,K)
                     const float* __restrict__ clog,          // (B,T,K,3)
                     const float* __restrict__ wsc,           // (B,T,1)
                     const void*  __restrict__ live_raw,      // (B,T,K) bool, dtype sniffed
                     const int*   __restrict__ cid,           // (B,T,K)
                     const float* __restrict__ ofire,         // (B,T,K)
                     const int*   __restrict__ ocan,          // (B,T,K)
                     const float* __restrict__ ovld,          // (B,T,K)
                     const float* __restrict__ osw,           // (B,T,1)
                     const int*   __restrict__ ocid,          // (B,T,K)
                     float* __restrict__ out)                 // (5,)
{
    // ---- Inline live_mask dtype sniff (all blocks read same 64 words; L2 broadcast) ----
    // mode 0 = uint8 bytes, 1 = int32 words, 2 = float32 words
    __shared__ unsigned int s_or, s_f32;
    __shared__ int s_mode;
    if (threadIdx.x == 0) { s_or = 0u; s_f32 = 0u; }
    __syncthreads();
    if (threadIdx.x < 64) {
        unsigned int x = ((const unsigned int*)live_raw)[threadIdx.x];
        unsigned int f = (x == 0x3F800000u) ? 1u : 0u;
        unsigned int a = f ? 0u : x;
#pragma unroll
        for (int o = 16; o > 0; o >>= 1) {
            a |= __shfl_down_sync(FULLMASK, a, o);
            f |= __shfl_down_sync(FULLMASK, f, o);
        }
        if ((threadIdx.x & 31) == 0) { atomicOr(&s_or, a); atomicOr(&s_f32, f); }
    }
    __syncthreads();
    if (threadIdx.x == 0)
        s_mode = s_f32 ? 2 : ((s_or & ~1u) ? 0 : 1);
    __syncthreads();
    const int mode = s_mode;

    const unsigned int lane  = threadIdx.x & 31;
    const unsigned int rbase = lane & ~3u;   // 4-lane row group base within warp

    float fire_s = 0.f, m_s = 0.f, val_s = 0.f, can_s = 0.f, has_s = 0.f, w_s = 0.f;

#pragma unroll
    for (int it = 0; it < ITER; ++it) {
        const int g = blockIdx.x * NTHR + threadIdx.x + it * NTHREADS; // 4-elem group
        const int eb   = g << 2;        // first element of this group
        const int rowe = eb & ~15;      // first element of this row
        const int sub  = g & 3;         // which quarter of the row

        // ---- Vectorized loads (128-bit, perfectly coalesced) ----
        const int4   cd4 = ((const int4*)cid)[g];
        const int4   oc4 = ((const int4*)ocid)[g];
        const float4 th4 = ((const float4*)trig)[g];
        const float4 vv4 = ((const float4*)vld)[g];

        // live -> 4-bit mask
        unsigned int lmask4 = 0u;
        if (mode == 0) {
            unsigned int lw = ((const unsigned int*)live_raw)[g];
            if (lw & 0x000000FFu) lmask4 |= 1u;
            if (lw & 0x0000FF00u) lmask4 |= 2u;
            if (lw & 0x00FF0000u) lmask4 |= 4u;
            if (lw & 0xFF000000u) lmask4 |= 8u;
        } else if (mode == 1) {
            int4 li = ((const int4*)live_raw)[g];
            if (li.x) lmask4 |= 1u;
            if (li.y) lmask4 |= 2u;
            if (li.z) lmask4 |= 4u;
            if (li.w) lmask4 |= 8u;
        } else {
            float4 lf = ((const float4*)live_raw)[g];
            if (lf.x != 0.0f) lmask4 |= 1u;
            if (lf.y != 0.0f) lmask4 |= 2u;
            if (lf.z != 0.0f) lmask4 |= 4u;
            if (lf.w != 0.0f) lmask4 |= 8u;
        }

        // ---- Materialize all 16 row ocids via 16 shuffles (4 per lane) ----
        int ov[16];
#pragma unroll
        for (int j = 0; j < 4; ++j) {
            const int sl = rbase + j;
            ov[4*j+0] = __shfl_sync(FULLMASK, oc4.x, sl, 32);
            ov[4*j+1] = __shfl_sync(FULLMASK, oc4.y, sl, 32);
            ov[4*j+2] = __shfl_sync(FULLMASK, oc4.z, sl, 32);
            ov[4*j+3] = __shfl_sync(FULLMASK, oc4.w, sl, 32);
        }

        const int   carr[4]  = {cd4.x, cd4.y, cd4.z, cd4.w};
        const float tharr[4] = {th4.x, th4.y, th4.z, th4.w};
        const float vvarr[4] = {vv4.x, vv4.y, vv4.z, vv4.w};

#pragma unroll
        for (int i = 0; i < 4; ++i) {
            const int c = carr[i];
            // first-match scan (descending so the smallest ko wins)
            int idx = 16;
#pragma unroll
            for (int ko = 15; ko >= 0; --ko)
                if (ov[ko] == c) idx = ko;
            const bool fnd = (idx < 16) && (c != 0);
            const int  gidx = rowe + (fnd ? idx : 0);

            if ((lmask4 >> i) & 1u) {
                m_s += 1.0f;

                // gather targets: guaranteed L1 hits (row lines just loaded by this warp)
                const float tf = fnd ? __ldg(&ofire[gidx]) : 0.0f;
                const float tv = fnd ? __ldg(&ovld[gidx])  : 0.0f;
                const int   ct = fnd ? __ldg(&ocan[gidx])  : 0;

                float p = fminf(fmaxf(tharr[i], EPS_F), 1.0f - EPS_F);
                fire_s -= tf * __logf(p) + (1.0f - tf) * __logf(1.0f - p);

                float q = fminf(fmaxf(vvarr[i], EPS_F), 1.0f - EPS_F);
                val_s -= tv * __logf(q) + (1.0f - tv) * __logf(1.0f - q);

                if (ct > 0) {
                    const float* lp = clog + (size_t)(eb + i) * 3;
                    float x0 = lp[0], x1 = lp[1], x2 = lp[2];
                    float mx = fmaxf(x0, fmaxf(x1, x2));
                    float s  = __expf(x0 - mx) + __expf(x1 - mx) + __expf(x2 - mx);
                    int tgt = ct - 1;
                    tgt = tgt < 0 ? 0 : (tgt > 2 ? 2 : tgt);
                    float xt = (tgt == 0) ? x0 : ((tgt == 1) ? x1 : x2);
                    can_s += mx + __logf(s) - xt;
                    has_s += 1.0f;
                }
            }
        }

        // write-head BCE-with-logits: one per row (quarter 0 lane)
        if (sub == 0) {
            const int row = g >> 2;
            float wx = wsc[row], wy = osw[row];
            w_s += fmaxf(wx, 0.0f) - wx * wy + __logf(1.0f + __expf(-fabsf(wx)));
        }
    }

    // ---- Deterministic block reduction of 6 float accumulators ----
    __shared__ float sm[8][6];
    {
        float vals[6] = {fire_s, m_s, val_s, can_s, has_s, w_s};
#pragma unroll
        for (int j = 0; j < 6; ++j) vals[j] = warp_sum_f(vals[j]);
        const int wid = threadIdx.x >> 5, lid = threadIdx.x & 31;
        if (lid == 0) {
#pragma unroll
            for (int j = 0; j < 6; ++j) sm[wid][j] = vals[j];
        }
        __syncthreads();
        if (wid == 0) {
#pragma unroll
            for (int j = 0; j < 6; ++j) {
                float v = (lid < (NTHR / 32)) ? sm[lid][j] : 0.0f;
                v = warp_sum_f(v);
                if (lid == 0) g_part[j * NBLK + blockIdx.x] = v;
            }
        }
    }

    // ---- Last-block finalize (threadfence reduction) ----
    __shared__ int s_last;
    if (threadIdx.x == 0) {
        __threadfence();
        unsigned int t = atomicAdd(&g_sem, 1u);
        s_last = (t == NBLK - 1) ? 1 : 0;
    }
    __syncthreads();
    if (!s_last) return;

    __shared__ double smd[8];
    double tot[6];
#pragma unroll
    for (int j = 0; j < 6; ++j) {
        double v = 0.0;
        for (int i = threadIdx.x; i < NBLK; i += NTHR)
            v += (double)__ldcg(&g_part[j * NBLK + i]);
        v = warp_sum_d(v);
        const int wid = threadIdx.x >> 5, lid = threadIdx.x & 31;
        if (lid == 0) smd[wid] = v;
        __syncthreads();
        double r = 0.0;
        if (wid == 0) {
            r = (lid < (NTHR / 32)) ? smd[lid] : 0.0;
            r = warp_sum_d(r);
        }
        tot[j] = r;  // valid on thread 0
        __syncthreads();
    }
    if (threadIdx.x == 0) {
        double n     = fmax(tot[1], 1.0);
        double fire  = tot[0] / n;                                        // LAM_FIRE   = 1.0
        double canc  = (tot[4] > 0.0) ? tot[3] / fmax(tot[4], 1.0) : 0.0; // LAM_CANCEL = 1.0
        double valid = 0.5 * tot[2] / n;                                  // LAM_VALID  = 0.5
        double wr    = 0.5 * tot[5] / (double)BT_ROWS;                    // LAM_WRITE  = 0.5
        out[0] = (float)fire;
        out[1] = (float)canc;
        out[2] = (float)valid;
        out[3] = (float)wr;
        out[4] = (float)(fire + canc + valid + wr);
        g_sem = 0;   // reset for next graph replay
    }
}

extern "C" void kernel_launch(void* const* d_in, const int* in_sizes, int n_in,
                              void* d_out, int out_size)
{
    (void)in_sizes; (void)n_in; (void)out_size;
    lifecycle_fused<<<NBLK, NTHR>>>(
        (const float*)d_in[0],          // trigger_hazard
        (const float*)d_in[1],          // validity
        (const float*)d_in[2],          // cancel_logits
        (const float*)d_in[3],          // write_score
        d_in[4],                        // live_mask (dtype auto-detected)
        (const int*)d_in[5],            // contract_id
        (const float*)d_in[6],          // oracle_fire
        (const int*)d_in[7],            // oracle_cancel
        (const float*)d_in[8],          // oracle_valid
        (const float*)d_in[9],          // oracle_should_write
        (const int*)d_in[10],           // oracle_contract_id
        (float*)d_out);
}